// round 1
// baseline (speedup 1.0000x reference)
#include <cuda_runtime.h>
#include <cstdint>

#define BATCH 32
#define NSEQ 2048
#define DHEAD 128
#define TQ 128
#define TK 64
#define THREADS 256
#define KVSTRIDE 136   // floats per row for Q/K/V smem tiles (D=128 + pad 8)
#define PSTRIDE 68     // floats per row for P smem tile (64 + pad 4)
#define INV_SCALE 0.088388347648318447f  // 1/sqrt(128)

// smem layout (floats)
#define SM_Q_OFF 0
#define SM_K_OFF (TQ * KVSTRIDE)
#define SM_V_OFF (SM_K_OFF + TK * KVSTRIDE)
#define SM_P_OFF (SM_V_OFF + TK * KVSTRIDE)
#define SM_FLOATS (SM_P_OFF + TQ * PSTRIDE)
#define SM_BYTES (SM_FLOATS * 4)

__device__ __forceinline__ uint32_t f2tf32u(float x) {
    uint32_t u;
    asm("cvt.rna.tf32.f32 %0, %1;" : "=r"(u) : "f"(x));
    return u;
}

__device__ __forceinline__ void mma_tf32(float* c, const uint32_t* a, const uint32_t* b) {
    asm volatile(
        "mma.sync.aligned.m16n8k8.row.col.f32.tf32.tf32.f32 "
        "{%0,%1,%2,%3},{%4,%5,%6,%7},{%8,%9},{%0,%1,%2,%3};\n"
        : "+f"(c[0]), "+f"(c[1]), "+f"(c[2]), "+f"(c[3])
        : "r"(a[0]), "r"(a[1]), "r"(a[2]), "r"(a[3]), "r"(b[0]), "r"(b[1]));
}

// load a [rows x 128] fp32 tile from gmem into smem (stride KVSTRIDE), rounding to tf32
__device__ __forceinline__ void load_tile_tf32(float* dst, const float* src, int rows, int tid) {
    const float4* s4 = (const float4*)src;
    for (int i = tid; i < rows * 32; i += THREADS) {
        int r = i >> 5;
        int c4 = i & 31;
        float4 val = s4[(size_t)r * 32 + c4];
        float* d = dst + r * KVSTRIDE + c4 * 4;
        d[0] = __uint_as_float(f2tf32u(val.x));
        d[1] = __uint_as_float(f2tf32u(val.y));
        d[2] = __uint_as_float(f2tf32u(val.z));
        d[3] = __uint_as_float(f2tf32u(val.w));
    }
}

__global__ void __launch_bounds__(THREADS, 1)
attn_kernel(const float* __restrict__ gq, const float* __restrict__ gk,
            const float* __restrict__ gv, float* __restrict__ gattn,
            float* __restrict__ gout) {
    extern __shared__ float sm[];
    float* Qs = sm + SM_Q_OFF;
    float* Ks = sm + SM_K_OFF;
    float* Vs = sm + SM_V_OFF;
    float* Ps = sm + SM_P_OFF;

    const int qt = blockIdx.x;
    const int b = blockIdx.y;
    const int tid = threadIdx.x;
    const int wid = tid >> 5;
    const int lane = tid & 31;
    const int lq = lane >> 2;  // 0..7
    const int lr = lane & 3;   // 0..3

    const int wrow = wid * 16;                 // warp's first row within q-tile
    const int gi0 = qt * TQ + wrow + lq;       // global query row (pair: gi0, gi0+8)
    const int kt_hi = 2 * qt + 1;              // last key tile touching causal region

    // ---- load Q tile once (tf32-rounded) ----
    load_tile_tf32(Qs, gq + ((size_t)b * NSEQ + (size_t)qt * TQ) * DHEAD, TQ, tid);

    // ================= PASS 1: row sums l =================
    float lsum_a = 0.f, lsum_b = 0.f;
    for (int kt = 0; kt <= kt_hi; kt++) {
        __syncthreads();
        load_tile_tf32(Ks, gk + ((size_t)b * NSEQ + (size_t)kt * TK) * DHEAD, TK, tid);
        __syncthreads();

        float c[8][4];
#pragma unroll
        for (int nf = 0; nf < 8; nf++) {
            c[nf][0] = 0.f; c[nf][1] = 0.f; c[nf][2] = 0.f; c[nf][3] = 0.f;
        }
#pragma unroll
        for (int ks = 0; ks < 16; ks++) {
            uint32_t a[4];
            const float* qa = Qs + (wrow + lq) * KVSTRIDE + ks * 8 + lr;
            a[0] = __float_as_uint(qa[0]);
            a[2] = __float_as_uint(qa[4]);
            const float* qb = qa + 8 * KVSTRIDE;
            a[1] = __float_as_uint(qb[0]);
            a[3] = __float_as_uint(qb[4]);
#pragma unroll
            for (int nf = 0; nf < 8; nf++) {
                uint32_t bb[2];
                const float* kb = Ks + (nf * 8 + lq) * KVSTRIDE + ks * 8 + lr;
                bb[0] = __float_as_uint(kb[0]);
                bb[1] = __float_as_uint(kb[4]);
                mma_tf32(c[nf], a, bb);
            }
        }
        const int jbase = kt * TK + 2 * lr;
#pragma unroll
        for (int nf = 0; nf < 8; nf++) {
            int j0 = jbase + nf * 8;
            float p00 = (j0     <= gi0)     ? __expf(c[nf][0] * INV_SCALE) : 0.f;
            float p01 = (j0 + 1 <= gi0)     ? __expf(c[nf][1] * INV_SCALE) : 0.f;
            float p10 = (j0     <= gi0 + 8) ? __expf(c[nf][2] * INV_SCALE) : 0.f;
            float p11 = (j0 + 1 <= gi0 + 8) ? __expf(c[nf][3] * INV_SCALE) : 0.f;
            lsum_a += p00 + p01;
            lsum_b += p10 + p11;
        }
    }
    // reduce across the 4 lanes that share each row
    lsum_a += __shfl_xor_sync(0xffffffffu, lsum_a, 1);
    lsum_a += __shfl_xor_sync(0xffffffffu, lsum_a, 2);
    lsum_b += __shfl_xor_sync(0xffffffffu, lsum_b, 1);
    lsum_b += __shfl_xor_sync(0xffffffffu, lsum_b, 2);
    const float linv_a = 1.0f / lsum_a;
    const float linv_b = 1.0f / lsum_b;

    // ================= PASS 2: write attn, accumulate O =================
    float o[16][4];
#pragma unroll
    for (int nf = 0; nf < 16; nf++) {
        o[nf][0] = 0.f; o[nf][1] = 0.f; o[nf][2] = 0.f; o[nf][3] = 0.f;
    }

    float* attn_row_a = gattn + ((size_t)b * NSEQ + gi0) * NSEQ;
    float* attn_row_b = attn_row_a + (size_t)8 * NSEQ;

    for (int kt = 0; kt <= kt_hi; kt++) {
        __syncthreads();
        load_tile_tf32(Ks, gk + ((size_t)b * NSEQ + (size_t)kt * TK) * DHEAD, TK, tid);
        load_tile_tf32(Vs, gv + ((size_t)b * NSEQ + (size_t)kt * TK) * DHEAD, TK, tid);
        __syncthreads();

        // recompute S (bit-identical to pass 1)
        float c[8][4];
#pragma unroll
        for (int nf = 0; nf < 8; nf++) {
            c[nf][0] = 0.f; c[nf][1] = 0.f; c[nf][2] = 0.f; c[nf][3] = 0.f;
        }
#pragma unroll
        for (int ks = 0; ks < 16; ks++) {
            uint32_t a[4];
            const float* qa = Qs + (wrow + lq) * KVSTRIDE + ks * 8 + lr;
            a[0] = __float_as_uint(qa[0]);
            a[2] = __float_as_uint(qa[4]);
            const float* qb = qa + 8 * KVSTRIDE;
            a[1] = __float_as_uint(qb[0]);
            a[3] = __float_as_uint(qb[4]);
#pragma unroll
            for (int nf = 0; nf < 8; nf++) {
                uint32_t bb[2];
                const float* kb = Ks + (nf * 8 + lq) * KVSTRIDE + ks * 8 + lr;
                bb[0] = __float_as_uint(kb[0]);
                bb[1] = __float_as_uint(kb[4]);
                mma_tf32(c[nf], a, bb);
            }
        }

        // normalize, write attn (fp32), stage P (tf32) for PV
        const int jbase = kt * TK + 2 * lr;
#pragma unroll
        for (int nf = 0; nf < 8; nf++) {
            int j0 = jbase + nf * 8;
            float p00 = (j0     <= gi0)     ? __expf(c[nf][0] * INV_SCALE) * linv_a : 0.f;
            float p01 = (j0 + 1 <= gi0)     ? __expf(c[nf][1] * INV_SCALE) * linv_a : 0.f;
            float p10 = (j0     <= gi0 + 8) ? __expf(c[nf][2] * INV_SCALE) * linv_b : 0.f;
            float p11 = (j0 + 1 <= gi0 + 8) ? __expf(c[nf][3] * INV_SCALE) * linv_b : 0.f;
            *(float2*)(attn_row_a + j0) = make_float2(p00, p01);
            *(float2*)(attn_row_b + j0) = make_float2(p10, p11);
            int pc = nf * 8 + 2 * lr;
            float* pra = Ps + (wrow + lq) * PSTRIDE + pc;
            pra[0] = __uint_as_float(f2tf32u(p00));
            pra[1] = __uint_as_float(f2tf32u(p01));
            float* prb = pra + 8 * PSTRIDE;
            prb[0] = __uint_as_float(f2tf32u(p10));
            prb[1] = __uint_as_float(f2tf32u(p11));
        }
        __syncwarp();

        // O += P @ V   (A = P[16 x 64] from smem, B = V[64 x 128] from smem)
#pragma unroll
        for (int ks = 0; ks < 8; ks++) {
            uint32_t a[4];
            const float* pa = Ps + (wrow + lq) * PSTRIDE + ks * 8 + lr;
            a[0] = __float_as_uint(pa[0]);
            a[2] = __float_as_uint(pa[4]);
            const float* pb = pa + 8 * PSTRIDE;
            a[1] = __float_as_uint(pb[0]);
            a[3] = __float_as_uint(pb[4]);
#pragma unroll
            for (int nf = 0; nf < 16; nf++) {
                uint32_t bb[2];
                const float* vb = Vs + (ks * 8 + lr) * KVSTRIDE + nf * 8 + lq;
                bb[0] = __float_as_uint(vb[0]);
                bb[1] = __float_as_uint(vb[4 * KVSTRIDE]);
                mma_tf32(o[nf], a, bb);
            }
        }
    }

    // ---- zero-fill the strictly-masked key tiles (j >= (kt_hi+1)*64) ----
    {
        const int jz = (kt_hi + 1) * TK;
        if (jz < NSEQ) {
            const int zc4 = (NSEQ - jz) >> 2;  // float4's per row
            const float4 z4 = make_float4(0.f, 0.f, 0.f, 0.f);
            float* base = gattn + ((size_t)b * NSEQ + (size_t)qt * TQ) * NSEQ + jz;
            for (int i = tid; i < TQ * zc4; i += THREADS) {
                int r = i / zc4;
                int cc = i - r * zc4;
                *(float4*)(base + (size_t)r * NSEQ + cc * 4) = z4;
            }
        }
    }

    // ---- write O ----
    float* orow_a = gout + ((size_t)b * NSEQ + gi0) * DHEAD;
    float* orow_b = orow_a + 8 * DHEAD;
#pragma unroll
    for (int nf = 0; nf < 16; nf++) {
        int d0 = nf * 8 + 2 * lr;
        *(float2*)(orow_a + d0) = make_float2(o[nf][0], o[nf][1]);
        *(float2*)(orow_b + d0) = make_float2(o[nf][2], o[nf][3]);
    }
}

extern "C" void kernel_launch(void* const* d_in, const int* in_sizes, int n_in,
                              void* d_out, int out_size) {
    const float* q = (const float*)d_in[0];
    const float* k = (const float*)d_in[1];
    const float* v = (const float*)d_in[2];
    // mask (d_in[3]) is a fixed causal mask; applied analytically in-kernel.
    float* attn = (float*)d_out;
    float* out = attn + (size_t)BATCH * NSEQ * NSEQ;

    cudaFuncSetAttribute(attn_kernel, cudaFuncAttributeMaxDynamicSharedMemorySize, SM_BYTES);
    dim3 grid(NSEQ / TQ, BATCH);
    attn_kernel<<<grid, THREADS, SM_BYTES>>>(q, k, v, attn, out);
}

// round 2
// speedup vs baseline: 1.0182x; 1.0182x over previous
#include <cuda_runtime.h>
#include <cstdint>

#define BATCH 32
#define NSEQ 2048
#define DHEAD 128
#define TQ 128
#define TK 64
#define THREADS 512
#define KVSTRIDE 136   // floats per row for Q/K/V smem tiles (D=128 + pad 8)
#define PSTRIDE 68     // floats per row for P smem tile (64 + pad 4)
#define INV_SCALE 0.088388347648318447f  // 1/sqrt(128)

// smem layout (floats)
#define SM_Q_OFF 0
#define SM_K_OFF (TQ * KVSTRIDE)
#define SM_V_OFF (SM_K_OFF + TK * KVSTRIDE)
#define SM_P_OFF (SM_V_OFF + TK * KVSTRIDE)
#define SM_FLOATS (SM_P_OFF + TQ * PSTRIDE)
#define SM_BYTES (SM_FLOATS * 4)

// row-sum reciprocals, written by main kernel, read by rescale kernel
__device__ float g_linv[BATCH * NSEQ];

__device__ __forceinline__ uint32_t f2tf32u(float x) {
    uint32_t u;
    asm("cvt.rna.tf32.f32 %0, %1;" : "=r"(u) : "f"(x));
    return u;
}

__device__ __forceinline__ void mma_tf32(float* c, const uint32_t* a, const uint32_t* b) {
    asm volatile(
        "mma.sync.aligned.m16n8k8.row.col.f32.tf32.tf32.f32 "
        "{%0,%1,%2,%3},{%4,%5,%6,%7},{%8,%9},{%0,%1,%2,%3};\n"
        : "+f"(c[0]), "+f"(c[1]), "+f"(c[2]), "+f"(c[3])
        : "r"(a[0]), "r"(a[1]), "r"(a[2]), "r"(a[3]), "r"(b[0]), "r"(b[1]));
}

// load a [rows x 128] fp32 tile from gmem into smem (stride KVSTRIDE), rounding to tf32
__device__ __forceinline__ void load_tile_tf32(float* dst, const float* src, int rows, int tid) {
    const float4* s4 = (const float4*)src;
    for (int i = tid; i < rows * 32; i += THREADS) {
        int r = i >> 5;
        int c4 = i & 31;
        float4 val = s4[(size_t)r * 32 + c4];
        float* d = dst + r * KVSTRIDE + c4 * 4;
        d[0] = __uint_as_float(f2tf32u(val.x));
        d[1] = __uint_as_float(f2tf32u(val.y));
        d[2] = __uint_as_float(f2tf32u(val.z));
        d[3] = __uint_as_float(f2tf32u(val.w));
    }
}

__global__ void __launch_bounds__(THREADS, 1)
attn_kernel(const float* __restrict__ gq, const float* __restrict__ gk,
            const float* __restrict__ gv, float* __restrict__ gattn,
            float* __restrict__ gout) {
    extern __shared__ float sm[];
    float* Qs = sm + SM_Q_OFF;
    float* Ks = sm + SM_K_OFF;
    float* Vs = sm + SM_V_OFF;
    float* Ps = sm + SM_P_OFF;

    const int qt = blockIdx.x;
    const int b = blockIdx.y;
    const int tid = threadIdx.x;
    const int wid = tid >> 5;
    const int lane = tid & 31;
    const int lq = lane >> 2;  // 0..7
    const int lr = lane & 3;   // 0..3

    const int wrow = (wid >> 1) * 16;          // warp's first row within q-tile (8 groups)
    const int half = wid & 1;                  // column-half specialization
    const int ch = half * 32;                  // S column offset within k-tile
    const int dh = half * 64;                  // O d-column offset
    const int gi0 = qt * TQ + wrow + lq;       // global query row (pair: gi0, gi0+8)
    const int kt_hi = 2 * qt + 1;              // last key tile touching causal region

    // ---- load Q tile once (tf32-rounded) ----
    load_tile_tf32(Qs, gq + ((size_t)b * NSEQ + (size_t)qt * TQ) * DHEAD, TQ, tid);

    // O accumulators: 8 n-frags over this warp's 64 d-columns
    float o[8][4];
#pragma unroll
    for (int nf = 0; nf < 8; nf++) {
        o[nf][0] = 0.f; o[nf][1] = 0.f; o[nf][2] = 0.f; o[nf][3] = 0.f;
    }
    float lsum_a = 0.f, lsum_b = 0.f;  // partial row sums (this warp's column half)

    float* attn_row_a = gattn + ((size_t)b * NSEQ + gi0) * NSEQ;
    float* attn_row_b = attn_row_a + (size_t)8 * NSEQ;

    for (int kt = 0; kt <= kt_hi; kt++) {
        __syncthreads();
        load_tile_tf32(Ks, gk + ((size_t)b * NSEQ + (size_t)kt * TK) * DHEAD, TK, tid);
        load_tile_tf32(Vs, gv + ((size_t)b * NSEQ + (size_t)kt * TK) * DHEAD, TK, tid);
        __syncthreads();

        // ---- S = Q K^T  (this warp: 16 rows x 32 cols) ----
        float c[4][4];
#pragma unroll
        for (int nf = 0; nf < 4; nf++) {
            c[nf][0] = 0.f; c[nf][1] = 0.f; c[nf][2] = 0.f; c[nf][3] = 0.f;
        }
#pragma unroll
        for (int ks = 0; ks < 16; ks++) {
            uint32_t a[4];
            const float* qa = Qs + (wrow + lq) * KVSTRIDE + ks * 8 + lr;
            a[0] = __float_as_uint(qa[0]);
            a[2] = __float_as_uint(qa[4]);
            const float* qb = qa + 8 * KVSTRIDE;
            a[1] = __float_as_uint(qb[0]);
            a[3] = __float_as_uint(qb[4]);
#pragma unroll
            for (int nf = 0; nf < 4; nf++) {
                uint32_t bb[2];
                const float* kb = Ks + (ch + nf * 8 + lq) * KVSTRIDE + ks * 8 + lr;
                bb[0] = __float_as_uint(kb[0]);
                bb[1] = __float_as_uint(kb[4]);
                mma_tf32(c[nf], a, bb);
            }
        }

        // ---- exp (unnormalized), accumulate l, write attn, stage P ----
        const int jbase = kt * TK + ch + 2 * lr;
#pragma unroll
        for (int nf = 0; nf < 4; nf++) {
            int j0 = jbase + nf * 8;
            float p00 = (j0     <= gi0)     ? __expf(c[nf][0] * INV_SCALE) : 0.f;
            float p01 = (j0 + 1 <= gi0)     ? __expf(c[nf][1] * INV_SCALE) : 0.f;
            float p10 = (j0     <= gi0 + 8) ? __expf(c[nf][2] * INV_SCALE) : 0.f;
            float p11 = (j0 + 1 <= gi0 + 8) ? __expf(c[nf][3] * INV_SCALE) : 0.f;
            lsum_a += p00 + p01;
            lsum_b += p10 + p11;
            *(float2*)(attn_row_a + j0) = make_float2(p00, p01);
            *(float2*)(attn_row_b + j0) = make_float2(p10, p11);
            int pc = ch + nf * 8 + 2 * lr;
            float* pra = Ps + (wrow + lq) * PSTRIDE + pc;
            pra[0] = __uint_as_float(f2tf32u(p00));
            pra[1] = __uint_as_float(f2tf32u(p01));
            float* prb = pra + 8 * PSTRIDE;
            prb[0] = __uint_as_float(f2tf32u(p10));
            prb[1] = __uint_as_float(f2tf32u(p11));
        }
        __syncthreads();   // P tile shared across the two column-half warps

        // ---- O += P @ V  (this warp: 16 rows x 64 d-cols) ----
#pragma unroll
        for (int ks = 0; ks < 8; ks++) {
            uint32_t a[4];
            const float* pa = Ps + (wrow + lq) * PSTRIDE + ks * 8 + lr;
            a[0] = __float_as_uint(pa[0]);
            a[2] = __float_as_uint(pa[4]);
            const float* pb = pa + 8 * PSTRIDE;
            a[1] = __float_as_uint(pb[0]);
            a[3] = __float_as_uint(pb[4]);
#pragma unroll
            for (int nf = 0; nf < 8; nf++) {
                uint32_t bb[2];
                const float* vb = Vs + (ks * 8 + lr) * KVSTRIDE + dh + nf * 8 + lq;
                bb[0] = __float_as_uint(vb[0]);
                bb[1] = __float_as_uint(vb[4 * KVSTRIDE]);
                mma_tf32(o[nf], a, bb);
            }
        }
    }

    // ---- combine the two column-half partial row sums via smem ----
    lsum_a += __shfl_xor_sync(0xffffffffu, lsum_a, 1);
    lsum_a += __shfl_xor_sync(0xffffffffu, lsum_a, 2);
    lsum_b += __shfl_xor_sync(0xffffffffu, lsum_b, 1);
    lsum_b += __shfl_xor_sync(0xffffffffu, lsum_b, 2);
    __syncthreads();   // all PV reads of Ps done; reuse Ps as scratch
    if (lr == 0) {
        Ps[(wrow + lq) * 2 + half] = lsum_a;
        Ps[(wrow + lq + 8) * 2 + half] = lsum_b;
    }
    __syncthreads();
    const float linv_a = 1.0f / (Ps[(wrow + lq) * 2] + Ps[(wrow + lq) * 2 + 1]);
    const float linv_b = 1.0f / (Ps[(wrow + lq + 8) * 2] + Ps[(wrow + lq + 8) * 2 + 1]);
    if (half == 0 && lr == 0) {
        g_linv[b * NSEQ + gi0] = linv_a;
        g_linv[b * NSEQ + gi0 + 8] = linv_b;
    }

    // ---- zero-fill the strictly-masked key region (j >= (kt_hi+1)*64) ----
    {
        const int jz = (kt_hi + 1) * TK;
        if (jz < NSEQ) {
            const int zc4 = (NSEQ - jz) >> 2;  // float4's per row
            const float4 z4 = make_float4(0.f, 0.f, 0.f, 0.f);
            float* base = gattn + ((size_t)b * NSEQ + (size_t)qt * TQ) * NSEQ + jz;
            for (int i = tid; i < TQ * zc4; i += THREADS) {
                int r = i / zc4;
                int cc = i - r * zc4;
                *(float4*)(base + (size_t)r * NSEQ + cc * 4) = z4;
            }
        }
    }

    // ---- write O (normalized) ----
    float* orow_a = gout + ((size_t)b * NSEQ + gi0) * DHEAD;
    float* orow_b = orow_a + 8 * DHEAD;
#pragma unroll
    for (int nf = 0; nf < 8; nf++) {
        int d0 = dh + nf * 8 + 2 * lr;
        *(float2*)(orow_a + d0) = make_float2(o[nf][0] * linv_a, o[nf][1] * linv_a);
        *(float2*)(orow_b + d0) = make_float2(o[nf][2] * linv_b, o[nf][3] * linv_b);
    }
}

// rescale the causal (lower-triangular) part of attn by 1/l; one warp per row
__global__ void __launch_bounds__(256)
rescale_kernel(float* __restrict__ gattn) {
    const int row = blockIdx.x * 8 + (threadIdx.x >> 5);  // b*NSEQ + i
    const int lane = threadIdx.x & 31;
    const int i = row & (NSEQ - 1);
    const float linv = g_linv[row];
    float* p = gattn + (size_t)row * NSEQ;
    const int n = i + 1;          // valid entries: j in [0, i]
    const int nvec = n & ~3;      // float4-aligned prefix
    for (int j = lane * 4; j < nvec; j += 128) {
        float4 v = *(float4*)(p + j);
        v.x *= linv; v.y *= linv; v.z *= linv; v.w *= linv;
        *(float4*)(p + j) = v;
    }
    if (lane < (n - nvec)) {
        p[nvec + lane] *= linv;
    }
}

extern "C" void kernel_launch(void* const* d_in, const int* in_sizes, int n_in,
                              void* d_out, int out_size) {
    const float* q = (const float*)d_in[0];
    const float* k = (const float*)d_in[1];
    const float* v = (const float*)d_in[2];
    // mask (d_in[3]) is a fixed causal mask; applied analytically in-kernel.
    float* attn = (float*)d_out;
    float* out = attn + (size_t)BATCH * NSEQ * NSEQ;

    cudaFuncSetAttribute(attn_kernel, cudaFuncAttributeMaxDynamicSharedMemorySize, SM_BYTES);
    dim3 grid(NSEQ / TQ, BATCH);
    attn_kernel<<<grid, THREADS, SM_BYTES>>>(q, k, v, attn, out);

    // normalize the causal part of attn (masked part is already exact zeros)
    rescale_kernel<<<(BATCH * NSEQ) / 8, 256>>>(attn);
}

// round 3
// speedup vs baseline: 1.1941x; 1.1727x over previous
#include <cuda_runtime.h>
#include <cstdint>

#define BATCH 32
#define NSEQ 2048
#define DHEAD 128
#define TQ 128
#define TK 64
#define THREADS 512
#define KVSTRIDE 136   // floats per row for Q/K smem tiles (128 + pad 8); mod 32 == 8
#define VSTRIDE 72     // floats per row for VT / P tiles (64 + pad 8); mod 32 == 8
#define INV_SCALE 0.088388347648318447f  // 1/sqrt(128)

// smem layout (floats)
#define SM_Q_OFF 0
#define SM_K_OFF (TQ * KVSTRIDE)
#define SM_V_OFF (SM_K_OFF + TK * KVSTRIDE)            // VT: [128 d][72]
#define SM_P_OFF (SM_V_OFF + DHEAD * VSTRIDE)          // P:  [128 q][72]
#define SM_FLOATS (SM_P_OFF + TQ * VSTRIDE)
#define SM_BYTES (SM_FLOATS * 4)

// row-sum reciprocals, written by main kernel, read by rescale kernel
__device__ float g_linv[BATCH * NSEQ];

__device__ __forceinline__ float f2tf32(float x) {
    uint32_t u;
    asm("cvt.rna.tf32.f32 %0, %1;" : "=r"(u) : "f"(x));
    return __uint_as_float(u);
}

__device__ __forceinline__ void mma_tf32(float* c, const uint32_t* a, const uint32_t* b) {
    asm volatile(
        "mma.sync.aligned.m16n8k8.row.col.f32.tf32.tf32.f32 "
        "{%0,%1,%2,%3},{%4,%5,%6,%7},{%8,%9},{%0,%1,%2,%3};\n"
        : "+f"(c[0]), "+f"(c[1]), "+f"(c[2]), "+f"(c[3])
        : "r"(a[0]), "r"(a[1]), "r"(a[2]), "r"(a[3]), "r"(b[0]), "r"(b[1]));
}

// Load a [rows x 128] fp32 tile (row-major) into smem with stride KVSTRIDE,
// tf32-rounded, with each 8-float group permuted to [x0,x4,x1,x5,x2,x6,x3,x7]
// so MMA fragment pairs (d, d+4) are adjacent (enables LDS.64).
__device__ __forceinline__ void load_tile_perm(float* dst, const float* src, int rows, int tid) {
    const float4* s4 = (const float4*)src;
    const int units = rows * 16;  // 8-float groups
    for (int u = tid; u < units; u += THREADS) {
        int r = u >> 4;
        int c8 = u & 15;
        float4 v0 = s4[r * 32 + c8 * 2];
        float4 v1 = s4[r * 32 + c8 * 2 + 1];
        float* d = dst + r * KVSTRIDE + c8 * 8;
        *(float4*)(d)     = make_float4(f2tf32(v0.x), f2tf32(v1.x), f2tf32(v0.y), f2tf32(v1.y));
        *(float4*)(d + 4) = make_float4(f2tf32(v0.z), f2tf32(v1.z), f2tf32(v0.w), f2tf32(v1.w));
    }
}

// Load V [64 k x 128 d] transposed into VT[d][k] (stride VSTRIDE), tf32-rounded,
// with the k index permuted within 8-groups (pairs (k, k+4) adjacent).
__device__ __forceinline__ void load_vt_perm(float* vt, const float* src, int tid) {
    const float4* s4 = (const float4*)src;
    for (int i = tid; i < TK * 32; i += THREADS) {
        int r = i & 63;        // key row
        int d4 = i >> 6;       // float4 index along d
        float4 v = s4[r * 32 + d4];
        int cpos = (r & ~7) + (((r & 3) << 1) | ((r & 4) >> 2));
        float* base = vt + (4 * d4) * VSTRIDE + cpos;
        base[0 * VSTRIDE] = f2tf32(v.x);
        base[1 * VSTRIDE] = f2tf32(v.y);
        base[2 * VSTRIDE] = f2tf32(v.z);
        base[3 * VSTRIDE] = f2tf32(v.w);
    }
}

__global__ void __launch_bounds__(THREADS, 1)
attn_kernel(const float* __restrict__ gq, const float* __restrict__ gk,
            const float* __restrict__ gv, float* __restrict__ gattn,
            float* __restrict__ gout) {
    extern __shared__ float sm[];
    float* Qs = sm + SM_Q_OFF;
    float* Ks = sm + SM_K_OFF;
    float* Vt = sm + SM_V_OFF;
    float* Ps = sm + SM_P_OFF;

    const int qt = blockIdx.x;
    const int b = blockIdx.y;
    const int tid = threadIdx.x;
    const int wid = tid >> 5;
    const int lane = tid & 31;
    const int lq = lane >> 2;  // 0..7
    const int lr = lane & 3;   // 0..3

    const int wrow = (wid >> 1) * 16;          // warp's first row within q-tile
    const int half = wid & 1;                  // column-half specialization
    const int ch = half * 32;                  // S column offset within k-tile
    const int dh = half * 64;                  // O d-column offset
    const int gi0 = qt * TQ + wrow + lq;       // global query row (pair: gi0, gi0+8)
    const int kt_hi = 2 * qt + 1;              // last key tile touching causal region

    // ---- load Q tile once (tf32-rounded, permuted) ----
    load_tile_perm(Qs, gq + ((size_t)b * NSEQ + (size_t)qt * TQ) * DHEAD, TQ, tid);

    // O accumulators: 8 n-frags over this warp's 64 d-columns
    float o[8][4];
#pragma unroll
    for (int nf = 0; nf < 8; nf++) {
        o[nf][0] = 0.f; o[nf][1] = 0.f; o[nf][2] = 0.f; o[nf][3] = 0.f;
    }
    float lsum_a = 0.f, lsum_b = 0.f;  // partial row sums (this warp's column half)

    float* attn_row_a = gattn + ((size_t)b * NSEQ + gi0) * NSEQ;
    float* attn_row_b = attn_row_a + (size_t)8 * NSEQ;

    // permuted in-group position for P stores: p00 -> pp, p01 -> pp+2
    const int pp = ((lr & 1) << 2) | (lr >> 1);

    for (int kt = 0; kt <= kt_hi; kt++) {
        __syncthreads();
        load_tile_perm(Ks, gk + ((size_t)b * NSEQ + (size_t)kt * TK) * DHEAD, TK, tid);
        load_vt_perm(Vt, gv + ((size_t)b * NSEQ + (size_t)kt * TK) * DHEAD, tid);
        __syncthreads();

        // ---- S = Q K^T  (this warp: 16 rows x 32 cols) ----
        float c[4][4];
#pragma unroll
        for (int nf = 0; nf < 4; nf++) {
            c[nf][0] = 0.f; c[nf][1] = 0.f; c[nf][2] = 0.f; c[nf][3] = 0.f;
        }
#pragma unroll
        for (int ks = 0; ks < 16; ks++) {
            uint32_t a[4];
            float2 a01 = *(const float2*)(Qs + (wrow + lq) * KVSTRIDE + ks * 8 + 2 * lr);
            float2 a23 = *(const float2*)(Qs + (wrow + lq + 8) * KVSTRIDE + ks * 8 + 2 * lr);
            a[0] = __float_as_uint(a01.x);
            a[2] = __float_as_uint(a01.y);
            a[1] = __float_as_uint(a23.x);
            a[3] = __float_as_uint(a23.y);
#pragma unroll
            for (int nf = 0; nf < 4; nf++) {
                float2 bv = *(const float2*)(Ks + (ch + nf * 8 + lq) * KVSTRIDE + ks * 8 + 2 * lr);
                uint32_t bb[2];
                bb[0] = __float_as_uint(bv.x);
                bb[1] = __float_as_uint(bv.y);
                mma_tf32(c[nf], a, bb);
            }
        }

        // ---- exp (unnormalized), accumulate l, write attn, stage P (permuted) ----
        const int jbase = kt * TK + ch + 2 * lr;
#pragma unroll
        for (int nf = 0; nf < 4; nf++) {
            int j0 = jbase + nf * 8;
            float p00 = (j0     <= gi0)     ? __expf(c[nf][0] * INV_SCALE) : 0.f;
            float p01 = (j0 + 1 <= gi0)     ? __expf(c[nf][1] * INV_SCALE) : 0.f;
            float p10 = (j0     <= gi0 + 8) ? __expf(c[nf][2] * INV_SCALE) : 0.f;
            float p11 = (j0 + 1 <= gi0 + 8) ? __expf(c[nf][3] * INV_SCALE) : 0.f;
            lsum_a += p00 + p01;
            lsum_b += p10 + p11;
            *(float2*)(attn_row_a + j0) = make_float2(p00, p01);
            *(float2*)(attn_row_b + j0) = make_float2(p10, p11);
            float* pr = Ps + (wrow + lq) * VSTRIDE + ch + nf * 8;
            pr[pp]     = f2tf32(p00);
            pr[pp + 2] = f2tf32(p01);
            float* prb = pr + 8 * VSTRIDE;
            prb[pp]     = f2tf32(p10);
            prb[pp + 2] = f2tf32(p11);
        }
        __syncthreads();   // P tile shared across the two column-half warps

        // ---- O += P @ V  (this warp: 16 rows x 64 d-cols) ----
#pragma unroll
        for (int ks = 0; ks < 8; ks++) {
            uint32_t a[4];
            float2 a01 = *(const float2*)(Ps + (wrow + lq) * VSTRIDE + ks * 8 + 2 * lr);
            float2 a23 = *(const float2*)(Ps + (wrow + lq + 8) * VSTRIDE + ks * 8 + 2 * lr);
            a[0] = __float_as_uint(a01.x);
            a[2] = __float_as_uint(a01.y);
            a[1] = __float_as_uint(a23.x);
            a[3] = __float_as_uint(a23.y);
#pragma unroll
            for (int nf = 0; nf < 8; nf++) {
                float2 bv = *(const float2*)(Vt + (dh + nf * 8 + lq) * VSTRIDE + ks * 8 + 2 * lr);
                uint32_t bb[2];
                bb[0] = __float_as_uint(bv.x);
                bb[1] = __float_as_uint(bv.y);
                mma_tf32(o[nf], a, bb);
            }
        }
    }

    // ---- combine the two column-half partial row sums via smem ----
    lsum_a += __shfl_xor_sync(0xffffffffu, lsum_a, 1);
    lsum_a += __shfl_xor_sync(0xffffffffu, lsum_a, 2);
    lsum_b += __shfl_xor_sync(0xffffffffu, lsum_b, 1);
    lsum_b += __shfl_xor_sync(0xffffffffu, lsum_b, 2);
    __syncthreads();   // all PV reads of Ps done; reuse Ps as scratch
    if (lr == 0) {
        Ps[(wrow + lq) * 2 + half] = lsum_a;
        Ps[(wrow + lq + 8) * 2 + half] = lsum_b;
    }
    __syncthreads();
    const float linv_a = 1.0f / (Ps[(wrow + lq) * 2] + Ps[(wrow + lq) * 2 + 1]);
    const float linv_b = 1.0f / (Ps[(wrow + lq + 8) * 2] + Ps[(wrow + lq + 8) * 2 + 1]);
    if (half == 0 && lr == 0) {
        g_linv[b * NSEQ + gi0] = linv_a;
        g_linv[b * NSEQ + gi0 + 8] = linv_b;
    }

    // ---- zero-fill the strictly-masked key region (j >= (kt_hi+1)*64) ----
    {
        const int jz = (kt_hi + 1) * TK;
        if (jz < NSEQ) {
            const int zc4 = (NSEQ - jz) >> 2;  // float4's per row
            const float4 z4 = make_float4(0.f, 0.f, 0.f, 0.f);
            float* base = gattn + ((size_t)b * NSEQ + (size_t)qt * TQ) * NSEQ + jz;
            for (int i = tid; i < TQ * zc4; i += THREADS) {
                int r = i / zc4;
                int cc = i - r * zc4;
                *(float4*)(base + (size_t)r * NSEQ + cc * 4) = z4;
            }
        }
    }

    // ---- write O (normalized) ----
    float* orow_a = gout + ((size_t)b * NSEQ + gi0) * DHEAD;
    float* orow_b = orow_a + 8 * DHEAD;
#pragma unroll
    for (int nf = 0; nf < 8; nf++) {
        int d0 = dh + nf * 8 + 2 * lr;
        *(float2*)(orow_a + d0) = make_float2(o[nf][0] * linv_a, o[nf][1] * linv_a);
        *(float2*)(orow_b + d0) = make_float2(o[nf][2] * linv_b, o[nf][3] * linv_b);
    }
}

// rescale the causal (lower-triangular) part of attn by 1/l; one warp per row
__global__ void __launch_bounds__(256)
rescale_kernel(float* __restrict__ gattn) {
    const int row = blockIdx.x * 8 + (threadIdx.x >> 5);  // b*NSEQ + i
    const int lane = threadIdx.x & 31;
    const int i = row & (NSEQ - 1);
    const float linv = g_linv[row];
    float* p = gattn + (size_t)row * NSEQ;
    const int n = i + 1;          // valid entries: j in [0, i]
    const int nvec = n & ~3;      // float4-aligned prefix
    for (int j = lane * 4; j < nvec; j += 128) {
        float4 v = *(float4*)(p + j);
        v.x *= linv; v.y *= linv; v.z *= linv; v.w *= linv;
        *(float4*)(p + j) = v;
    }
    if (lane < (n - nvec)) {
        p[nvec + lane] *= linv;
    }
}

extern "C" void kernel_launch(void* const* d_in, const int* in_sizes, int n_in,
                              void* d_out, int out_size) {
    const float* q = (const float*)d_in[0];
    const float* k = (const float*)d_in[1];
    const float* v = (const float*)d_in[2];
    // mask (d_in[3]) is a fixed causal mask; applied analytically in-kernel.
    float* attn = (float*)d_out;
    float* out = attn + (size_t)BATCH * NSEQ * NSEQ;

    cudaFuncSetAttribute(attn_kernel, cudaFuncAttributeMaxDynamicSharedMemorySize, SM_BYTES);
    dim3 grid(NSEQ / TQ, BATCH);
    attn_kernel<<<grid, THREADS, SM_BYTES>>>(q, k, v, attn, out);

    // normalize the causal part of attn (masked part is already exact zeros)
    rescale_kernel<<<(BATCH * NSEQ) / 8, 256>>>(attn);
}

// round 5
// speedup vs baseline: 1.4340x; 1.2010x over previous
#include <cuda_runtime.h>
#include <cstdint>

#define BATCH 32
#define NSEQ 2048
#define DHEAD 128
#define TQ 128
#define TK 64
#define THREADS 512
#define KVSTRIDE 136   // floats per row for Q/K smem tiles (128 + pad 8); mod 32 == 8
#define VSTRIDE 72     // floats per row for VT / P tiles (64 + pad 8); mod 32 == 8
#define INV_SCALE 0.088388347648318447f  // 1/sqrt(128)

// smem layout (floats)
#define SM_Q_OFF 0
#define SM_K_OFF (TQ * KVSTRIDE)
#define SM_V_OFF (SM_K_OFF + TK * KVSTRIDE)            // VT: [128 d][72]
#define SM_P_OFF (SM_V_OFF + DHEAD * VSTRIDE)          // P:  [128 q][72]
#define SM_FLOATS (SM_P_OFF + TQ * VSTRIDE)
#define SM_BYTES (SM_FLOATS * 4)

// row-sum reciprocals, written by main kernel, read by rescale kernel
__device__ float g_linv[BATCH * NSEQ];

__device__ __forceinline__ float f2tf32(float x) {
    uint32_t u;
    asm("cvt.rna.tf32.f32 %0, %1;" : "=r"(u) : "f"(x));
    return __uint_as_float(u);
}

__device__ __forceinline__ void mma_tf32(float* c, const uint32_t* a, const uint32_t* b) {
    asm volatile(
        "mma.sync.aligned.m16n8k8.row.col.f32.tf32.tf32.f32 "
        "{%0,%1,%2,%3},{%4,%5,%6,%7},{%8,%9},{%0,%1,%2,%3};\n"
        : "+f"(c[0]), "+f"(c[1]), "+f"(c[2]), "+f"(c[3])
        : "r"(a[0]), "r"(a[1]), "r"(a[2]), "r"(a[3]), "r"(b[0]), "r"(b[1]));
}

// ---- K-tile mapping helpers (blocked layout: permute 8-groups to [x0,x4,x1,x5,x2,x6,x3,x7]) ----
__device__ __forceinline__ void sts_k_unit(float* dst, int u, float4 v0, float4 v1) {
    int r = u >> 4;
    int c8 = u & 15;
    float* d = dst + r * KVSTRIDE + c8 * 8;
    *(float4*)(d)     = make_float4(f2tf32(v0.x), f2tf32(v1.x), f2tf32(v0.y), f2tf32(v1.y));
    *(float4*)(d + 4) = make_float4(f2tf32(v0.z), f2tf32(v1.z), f2tf32(v0.w), f2tf32(v1.w));
}

// load a [rows x 128] fp32 tile into smem (stride KVSTRIDE), tf32-rounded + permuted
__device__ __forceinline__ void load_tile_perm(float* dst, const float* src, int rows, int tid) {
    const float4* s4 = (const float4*)src;
    const int units = rows * 16;
    for (int u = tid; u < units; u += THREADS) {
        float4 v0 = s4[(u >> 4) * 32 + (u & 15) * 2];
        float4 v1 = s4[(u >> 4) * 32 + (u & 15) * 2 + 1];
        sts_k_unit(dst, u, v0, v1);
    }
}

// ---- VT mapping (V transposed, k-index permuted within 8-groups) ----
__device__ __forceinline__ void sts_v_unit(float* vt, int i, float4 v) {
    int k = i & 63;
    int d4 = i >> 6;
    int cpos = (k & ~7) + (((k & 3) << 1) | ((k & 4) >> 2));
    float* base = vt + (4 * d4) * VSTRIDE + cpos;
    base[0 * VSTRIDE] = f2tf32(v.x);
    base[1 * VSTRIDE] = f2tf32(v.y);
    base[2 * VSTRIDE] = f2tf32(v.z);
    base[3 * VSTRIDE] = f2tf32(v.w);
}

__device__ __forceinline__ void load_vt_perm(float* vt, const float* src, int tid) {
    const float4* s4 = (const float4*)src;
    for (int i = tid; i < TK * 32; i += THREADS) {
        sts_v_unit(vt, i, s4[(i & 63) * 32 + (i >> 6)]);
    }
}

__global__ void __launch_bounds__(THREADS, 1)
attn_kernel(const float* __restrict__ gq, const float* __restrict__ gk,
            const float* __restrict__ gv, float* __restrict__ gattn,
            float* __restrict__ gout) {
    extern __shared__ float sm[];
    float* Qs = sm + SM_Q_OFF;
    float* Ks = sm + SM_K_OFF;
    float* Vt = sm + SM_V_OFF;
    float* Ps = sm + SM_P_OFF;

    const int qt = blockIdx.x;
    const int b = blockIdx.y;
    const int tid = threadIdx.x;
    const int wid = tid >> 5;
    const int lane = tid & 31;
    const int lq = lane >> 2;  // 0..7
    const int lr = lane & 3;   // 0..3

    const int wrow = (wid >> 1) * 16;          // warp's first row within q-tile
    const int half = wid & 1;                  // column-half specialization
    const int ch = half * 32;                  // S column offset within k-tile
    const int dh = half * 64;                  // O d-column offset
    const int gi0 = qt * TQ + wrow + lq;       // global query row (pair: gi0, gi0+8)
    const int kt_hi = 2 * qt + 1;              // last key tile touching causal region

    // ---- prologue: Q tile + first K/V tiles ----
    load_tile_perm(Qs, gq + ((size_t)b * NSEQ + (size_t)qt * TQ) * DHEAD, TQ, tid);
    load_tile_perm(Ks, gk + ((size_t)b * NSEQ) * DHEAD, TK, tid);
    load_vt_perm(Vt, gv + ((size_t)b * NSEQ) * DHEAD, tid);

    float o[8][4];
#pragma unroll
    for (int nf = 0; nf < 8; nf++) {
        o[nf][0] = 0.f; o[nf][1] = 0.f; o[nf][2] = 0.f; o[nf][3] = 0.f;
    }
    float lsum_a = 0.f, lsum_b = 0.f;

    float* attn_row_a = gattn + ((size_t)b * NSEQ + gi0) * NSEQ;
    float* attn_row_b = attn_row_a + (size_t)8 * NSEQ;

    // permuted in-group position for P stores: p00 -> pp, p01 -> pp+2
    const int pp = ((lr & 1) << 2) | (lr >> 1);
    const int u0 = tid, u1 = tid + THREADS;   // this thread's two K-tile units

    __syncthreads();

    for (int kt = 0; kt <= kt_hi; kt++) {
        const bool has_next = (kt < kt_hi);

        // ---- prefetch next K tile into registers (LDG latency hides behind compute) ----
        float4 kp0, kp1, kp2, kp3;
        if (has_next) {
            const float4* ks4 = (const float4*)(gk + ((size_t)b * NSEQ + (size_t)(kt + 1) * TK) * DHEAD);
            kp0 = ks4[(u0 >> 4) * 32 + (u0 & 15) * 2];
            kp1 = ks4[(u0 >> 4) * 32 + (u0 & 15) * 2 + 1];
            kp2 = ks4[(u1 >> 4) * 32 + (u1 & 15) * 2];
            kp3 = ks4[(u1 >> 4) * 32 + (u1 & 15) * 2 + 1];
        }

        // ---- S = Q K^T  (this warp: 16 rows x 32 cols) ----
        float c[4][4];
#pragma unroll
        for (int nf = 0; nf < 4; nf++) {
            c[nf][0] = 0.f; c[nf][1] = 0.f; c[nf][2] = 0.f; c[nf][3] = 0.f;
        }
#pragma unroll
        for (int ks = 0; ks < 16; ks++) {
            uint32_t a[4];
            float2 a01 = *(const float2*)(Qs + (wrow + lq) * KVSTRIDE + ks * 8 + 2 * lr);
            float2 a23 = *(const float2*)(Qs + (wrow + lq + 8) * KVSTRIDE + ks * 8 + 2 * lr);
            a[0] = __float_as_uint(a01.x);
            a[2] = __float_as_uint(a01.y);
            a[1] = __float_as_uint(a23.x);
            a[3] = __float_as_uint(a23.y);
#pragma unroll
            for (int nf = 0; nf < 4; nf++) {
                float2 bv = *(const float2*)(Ks + (ch + nf * 8 + lq) * KVSTRIDE + ks * 8 + 2 * lr);
                uint32_t bb[2];
                bb[0] = __float_as_uint(bv.x);
                bb[1] = __float_as_uint(bv.y);
                mma_tf32(c[nf], a, bb);
            }
        }

        // ---- prefetch next V tile into registers ----
        float4 vp0, vp1, vp2, vp3;
        if (has_next) {
            const float4* vs4 = (const float4*)(gv + ((size_t)b * NSEQ + (size_t)(kt + 1) * TK) * DHEAD);
            vp0 = vs4[((tid)            & 63) * 32 + ((tid)            >> 6)];
            vp1 = vs4[((tid + 512)      & 63) * 32 + ((tid + 512)      >> 6)];
            vp2 = vs4[((tid + 1024)     & 63) * 32 + ((tid + 1024)     >> 6)];
            vp3 = vs4[((tid + 1536)     & 63) * 32 + ((tid + 1536)     >> 6)];
        }

        // ---- exp (unnormalized), accumulate l, write attn, stage P (permuted) ----
        const int jbase = kt * TK + ch + 2 * lr;
#pragma unroll
        for (int nf = 0; nf < 4; nf++) {
            int j0 = jbase + nf * 8;
            float p00 = (j0     <= gi0)     ? __expf(c[nf][0] * INV_SCALE) : 0.f;
            float p01 = (j0 + 1 <= gi0)     ? __expf(c[nf][1] * INV_SCALE) : 0.f;
            float p10 = (j0     <= gi0 + 8) ? __expf(c[nf][2] * INV_SCALE) : 0.f;
            float p11 = (j0 + 1 <= gi0 + 8) ? __expf(c[nf][3] * INV_SCALE) : 0.f;
            lsum_a += p00 + p01;
            lsum_b += p10 + p11;
            *(float2*)(attn_row_a + j0) = make_float2(p00, p01);
            *(float2*)(attn_row_b + j0) = make_float2(p10, p11);
            float* pr = Ps + (wrow + lq) * VSTRIDE + ch + nf * 8;
            pr[pp]     = f2tf32(p00);
            pr[pp + 2] = f2tf32(p01);
            float* prb = pr + 8 * VSTRIDE;
            prb[pp]     = f2tf32(p10);
            prb[pp + 2] = f2tf32(p11);
        }
        __syncthreads();   // QK done block-wide (K consumable), P visible

        // ---- store prefetched K into smem (overlaps PV MMA below) ----
        if (has_next) {
            sts_k_unit(Ks, u0, kp0, kp1);
            sts_k_unit(Ks, u1, kp2, kp3);
        }

        // ---- O += P @ V  (this warp: 16 rows x 64 d-cols) ----
#pragma unroll
        for (int ks = 0; ks < 8; ks++) {
            uint32_t a[4];
            float2 a01 = *(const float2*)(Ps + (wrow + lq) * VSTRIDE + ks * 8 + 2 * lr);
            float2 a23 = *(const float2*)(Ps + (wrow + lq + 8) * VSTRIDE + ks * 8 + 2 * lr);
            a[0] = __float_as_uint(a01.x);
            a[2] = __float_as_uint(a01.y);
            a[1] = __float_as_uint(a23.x);
            a[3] = __float_as_uint(a23.y);
#pragma unroll
            for (int nf = 0; nf < 8; nf++) {
                float2 bv = *(const float2*)(Vt + (dh + nf * 8 + lq) * VSTRIDE + ks * 8 + 2 * lr);
                uint32_t bb[2];
                bb[0] = __float_as_uint(bv.x);
                bb[1] = __float_as_uint(bv.y);
                mma_tf32(o[nf], a, bb);
            }
        }
        __syncthreads();   // PV done block-wide (V consumable)

        // ---- store prefetched V into smem ----
        if (has_next) {
            sts_v_unit(Vt, tid, vp0);
            sts_v_unit(Vt, tid + 512, vp1);
            sts_v_unit(Vt, tid + 1024, vp2);
            sts_v_unit(Vt, tid + 1536, vp3);
            __syncthreads();   // new K/V visible for next iteration
        }
    }

    // ---- combine the two column-half partial row sums via smem ----
    lsum_a += __shfl_xor_sync(0xffffffffu, lsum_a, 1);
    lsum_a += __shfl_xor_sync(0xffffffffu, lsum_a, 2);
    lsum_b += __shfl_xor_sync(0xffffffffu, lsum_b, 1);
    lsum_b += __shfl_xor_sync(0xffffffffu, lsum_b, 2);
    __syncthreads();   // all PV reads of Ps done; reuse Ps as scratch
    if (lr == 0) {
        Ps[(wrow + lq) * 2 + half] = lsum_a;
        Ps[(wrow + lq + 8) * 2 + half] = lsum_b;
    }
    __syncthreads();
    const float linv_a = 1.0f / (Ps[(wrow + lq) * 2] + Ps[(wrow + lq) * 2 + 1]);
    const float linv_b = 1.0f / (Ps[(wrow + lq + 8) * 2] + Ps[(wrow + lq + 8) * 2 + 1]);
    if (half == 0 && lr == 0) {
        g_linv[b * NSEQ + gi0] = linv_a;
        g_linv[b * NSEQ + gi0 + 8] = linv_b;
    }

    // ---- zero-fill the strictly-masked key region (j >= (kt_hi+1)*64) ----
    {
        const int jz = (kt_hi + 1) * TK;
        if (jz < NSEQ) {
            const int zc4 = (NSEQ - jz) >> 2;  // float4's per row
            const float4 z4 = make_float4(0.f, 0.f, 0.f, 0.f);
            float* base = gattn + ((size_t)b * NSEQ + (size_t)qt * TQ) * NSEQ + jz;
            for (int i = tid; i < TQ * zc4; i += THREADS) {
                int r = i / zc4;
                int cc = i - r * zc4;
                *(float4*)(base + (size_t)r * NSEQ + cc * 4) = z4;
            }
        }
    }

    // ---- write O (normalized) ----
    float* orow_a = gout + ((size_t)b * NSEQ + gi0) * DHEAD;
    float* orow_b = orow_a + 8 * DHEAD;
#pragma unroll
    for (int nf = 0; nf < 8; nf++) {
        int d0 = dh + nf * 8 + 2 * lr;
        *(float2*)(orow_a + d0) = make_float2(o[nf][0] * linv_a, o[nf][1] * linv_a);
        *(float2*)(orow_b + d0) = make_float2(o[nf][2] * linv_b, o[nf][3] * linv_b);
    }
}

// rescale the causal (lower-triangular) part of attn by 1/l; one warp per row
__global__ void __launch_bounds__(256)
rescale_kernel(float* __restrict__ gattn) {
    const int row = blockIdx.x * 8 + (threadIdx.x >> 5);  // b*NSEQ + i
    const int lane = threadIdx.x & 31;
    const int i = row & (NSEQ - 1);
    const float linv = g_linv[row];
    float* p = gattn + (size_t)row * NSEQ;
    const int n = i + 1;          // valid entries: j in [0, i]
    const int nvec = n & ~3;      // float4-aligned prefix
    for (int j = lane * 4; j < nvec; j += 128) {
        float4 v = *(float4*)(p + j);
        v.x *= linv; v.y *= linv; v.z *= linv; v.w *= linv;
        *(float4*)(p + j) = v;
    }
    if (lane < (n - nvec)) {
        p[nvec + lane] *= linv;
    }
}

extern "C" void kernel_launch(void* const* d_in, const int* in_sizes, int n_in,
                              void* d_out, int out_size) {
    const float* q = (const float*)d_in[0];
    const float* k = (const float*)d_in[1];
    const float* v = (const float*)d_in[2];
    // mask (d_in[3]) is a fixed causal mask; applied analytically in-kernel.
    float* attn = (float*)d_out;
    float* out = attn + (size_t)BATCH * NSEQ * NSEQ;

    cudaFuncSetAttribute(attn_kernel, cudaFuncAttributeMaxDynamicSharedMemorySize, SM_BYTES);
    dim3 grid(NSEQ / TQ, BATCH);
    attn_kernel<<<grid, THREADS, SM_BYTES>>>(q, k, v, attn, out);

    // normalize the causal part of attn (masked part is already exact zeros)
    rescale_kernel<<<(BATCH * NSEQ) / 8, 256>>>(attn);
}

// round 6
// speedup vs baseline: 1.6162x; 1.1271x over previous
#include <cuda_runtime.h>
#include <cstdint>

#define BATCH 32
#define NSEQ 2048
#define DHEAD 128
#define TQ 128
#define TK 64
#define THREADS 256
#define KSTRIDE 136   // Q/K smem row stride (floats); 136 mod 32 = 8 -> LDS.64 row-frags conflict-free
#define VSTRIDE 132   // V smem row stride (floats); 132 mod 32 = 4 -> LDS.32 col-frags conflict-free
#define INV_SCALE 0.088388347648318447f  // 1/sqrt(128)

// smem layout (floats)
#define SM_Q_OFF 0
#define SM_K_OFF (TQ * KSTRIDE)
#define SM_V_OFF (SM_K_OFF + TK * KSTRIDE)
#define SM_FLOATS (SM_V_OFF + TK * VSTRIDE)
#define SM_BYTES (SM_FLOATS * 4)

__device__ float g_linv[BATCH * NSEQ];

__device__ __forceinline__ float f2tf32(float x) {
    uint32_t u;
    asm("cvt.rna.tf32.f32 %0, %1;" : "=r"(u) : "f"(x));
    return __uint_as_float(u);
}

__device__ __forceinline__ void mma_tf32(float* c, const uint32_t* a, const uint32_t* b) {
    asm volatile(
        "mma.sync.aligned.m16n8k8.row.col.f32.tf32.tf32.f32 "
        "{%0,%1,%2,%3},{%4,%5,%6,%7},{%8,%9},{%0,%1,%2,%3};\n"
        : "+f"(c[0]), "+f"(c[1]), "+f"(c[2]), "+f"(c[3])
        : "r"(a[0]), "r"(a[1]), "r"(a[2]), "r"(a[3]), "r"(b[0]), "r"(b[1]));
}

__device__ __forceinline__ float4 cvt4(float4 v) {
    return make_float4(f2tf32(v.x), f2tf32(v.y), f2tf32(v.z), f2tf32(v.w));
}

// plain row-major copy (tf32-rounded): unit u -> row u>>5, float4-chunk u&31
template <int STRIDE>
__device__ __forceinline__ void sts_unit(float* dst, int u, float4 v) {
    *(float4*)(dst + (u >> 5) * STRIDE + (u & 31) * 4) = cvt4(v);
}

__global__ void __launch_bounds__(THREADS, 1)
attn_kernel(const float* __restrict__ gq, const float* __restrict__ gk,
            const float* __restrict__ gv, float* __restrict__ gattn,
            float* __restrict__ gout) {
    extern __shared__ float sm[];
    float* Qs = sm + SM_Q_OFF;
    float* Ks = sm + SM_K_OFF;
    float* Vs = sm + SM_V_OFF;

    const int qt = blockIdx.x;
    const int b = blockIdx.y;
    const int tid = threadIdx.x;
    const int wid = tid >> 5;
    const int lane = tid & 31;
    const int lq = lane >> 2;  // 0..7
    const int lr = lane & 3;   // 0..3

    const int wrow = wid * 16;                 // warp's first row within q-tile
    const int gi0 = qt * TQ + wrow + lq;       // global query row (pair: gi0, gi0+8)
    const int kt_hi = 2 * qt + 1;              // last key tile touching causal region

    // ---- prologue fills: Q (once), K0, V0 ----
    {
        const float4* q4 = (const float4*)(gq + ((size_t)b * NSEQ + (size_t)qt * TQ) * DHEAD);
        for (int u = tid; u < TQ * 32; u += THREADS) sts_unit<KSTRIDE>(Qs, u, q4[u]);
        const float4* k4 = (const float4*)(gk + (size_t)b * NSEQ * DHEAD);
        for (int u = tid; u < TK * 32; u += THREADS) sts_unit<KSTRIDE>(Ks, u, k4[u]);
        const float4* v4 = (const float4*)(gv + (size_t)b * NSEQ * DHEAD);
        for (int u = tid; u < TK * 32; u += THREADS) sts_unit<VSTRIDE>(Vs, u, v4[u]);
    }

    float o[16][4];
#pragma unroll
    for (int nf = 0; nf < 16; nf++) {
        o[nf][0] = 0.f; o[nf][1] = 0.f; o[nf][2] = 0.f; o[nf][3] = 0.f;
    }
    float lsum_a = 0.f, lsum_b = 0.f;

    float* attn_row_a = gattn + ((size_t)b * NSEQ + gi0) * NSEQ;
    float* attn_row_b = attn_row_a + (size_t)8 * NSEQ;

    __syncthreads();

    for (int kt = 0; kt <= kt_hi; kt++) {
        const bool has_next = (kt < kt_hi);

        // ---- register-prefetch next K and V tiles (raw; cvt at store time) ----
        float4 kp[8], vp[8];
        if (has_next) {
            const float4* k4 = (const float4*)(gk + ((size_t)b * NSEQ + (size_t)(kt + 1) * TK) * DHEAD);
            const float4* v4 = (const float4*)(gv + ((size_t)b * NSEQ + (size_t)(kt + 1) * TK) * DHEAD);
#pragma unroll
            for (int j = 0; j < 8; j++) kp[j] = k4[tid + j * THREADS];
#pragma unroll
            for (int j = 0; j < 8; j++) vp[j] = v4[tid + j * THREADS];
        }

        // ---- S = Q K^T  (warp: 16 rows x 64 cols) ----
        // k-slice mapping: MMA k-slot lr -> d = 8*ks+2*lr, slot lr+4 -> d = 8*ks+2*lr+1
        float c[8][4];
#pragma unroll
        for (int nf = 0; nf < 8; nf++) {
            c[nf][0] = 0.f; c[nf][1] = 0.f; c[nf][2] = 0.f; c[nf][3] = 0.f;
        }
#pragma unroll
        for (int ks = 0; ks < 16; ks++) {
            uint32_t a[4];
            float2 a01 = *(const float2*)(Qs + (wrow + lq) * KSTRIDE + ks * 8 + 2 * lr);
            float2 a23 = *(const float2*)(Qs + (wrow + lq + 8) * KSTRIDE + ks * 8 + 2 * lr);
            a[0] = __float_as_uint(a01.x);
            a[2] = __float_as_uint(a01.y);
            a[1] = __float_as_uint(a23.x);
            a[3] = __float_as_uint(a23.y);
#pragma unroll
            for (int nf = 0; nf < 8; nf++) {
                float2 bv = *(const float2*)(Ks + (nf * 8 + lq) * KSTRIDE + ks * 8 + 2 * lr);
                uint32_t bb[2];
                bb[0] = __float_as_uint(bv.x);
                bb[1] = __float_as_uint(bv.y);
                mma_tf32(c[nf], a, bb);
            }
        }

        // ---- exp (unnormalized), accumulate l, write attn, tf32-round P in regs ----
#pragma unroll
        for (int nf = 0; nf < 8; nf++) {
            int j0 = kt * TK + nf * 8 + 2 * lr;
            float p00 = (j0     <= gi0)     ? __expf(c[nf][0] * INV_SCALE) : 0.f;
            float p01 = (j0 + 1 <= gi0)     ? __expf(c[nf][1] * INV_SCALE) : 0.f;
            float p10 = (j0     <= gi0 + 8) ? __expf(c[nf][2] * INV_SCALE) : 0.f;
            float p11 = (j0 + 1 <= gi0 + 8) ? __expf(c[nf][3] * INV_SCALE) : 0.f;
            lsum_a += p00 + p01;
            lsum_b += p10 + p11;
            *(float2*)(attn_row_a + j0) = make_float2(p00, p01);
            *(float2*)(attn_row_b + j0) = make_float2(p10, p11);
            c[nf][0] = f2tf32(p00);
            c[nf][1] = f2tf32(p01);
            c[nf][2] = f2tf32(p10);
            c[nf][3] = f2tf32(p11);
        }

        // ---- O += P @ V  (A = c-regs; B = V rows, 2x LDS.32 per frag) ----
#pragma unroll
        for (int ks = 0; ks < 8; ks++) {
            uint32_t a[4];
            a[0] = __float_as_uint(c[ks][0]);
            a[1] = __float_as_uint(c[ks][2]);
            a[2] = __float_as_uint(c[ks][1]);
            a[3] = __float_as_uint(c[ks][3]);
            const float* vr0 = Vs + (ks * 8 + 2 * lr) * VSTRIDE + lq;
            const float* vr1 = vr0 + VSTRIDE;
#pragma unroll
            for (int nf = 0; nf < 16; nf++) {
                uint32_t bb[2];
                bb[0] = __float_as_uint(vr0[nf * 8]);
                bb[1] = __float_as_uint(vr1[nf * 8]);
                mma_tf32(o[nf], a, bb);
            }
        }
        __syncthreads();   // K/V consumable (QK + PV done block-wide)

        // ---- store prefetched K/V ----
        if (has_next) {
#pragma unroll
            for (int j = 0; j < 8; j++) sts_unit<KSTRIDE>(Ks, tid + j * THREADS, kp[j]);
#pragma unroll
            for (int j = 0; j < 8; j++) sts_unit<VSTRIDE>(Vs, tid + j * THREADS, vp[j]);
            __syncthreads();   // new K/V visible
        }
    }

    // ---- row sums (warp-local: full key range per warp) ----
    lsum_a += __shfl_xor_sync(0xffffffffu, lsum_a, 1);
    lsum_a += __shfl_xor_sync(0xffffffffu, lsum_a, 2);
    lsum_b += __shfl_xor_sync(0xffffffffu, lsum_b, 1);
    lsum_b += __shfl_xor_sync(0xffffffffu, lsum_b, 2);
    const float linv_a = 1.0f / lsum_a;
    const float linv_b = 1.0f / lsum_b;
    if (lr == 0) {
        g_linv[b * NSEQ + gi0] = linv_a;
        g_linv[b * NSEQ + gi0 + 8] = linv_b;
    }

    // ---- zero-fill the strictly-masked key region (j >= (kt_hi+1)*64) ----
    {
        const int jz = (kt_hi + 1) * TK;
        if (jz < NSEQ) {
            const int zc4 = (NSEQ - jz) >> 2;
            const float4 z4 = make_float4(0.f, 0.f, 0.f, 0.f);
            float* base = gattn + ((size_t)b * NSEQ + (size_t)qt * TQ) * NSEQ + jz;
            for (int i = tid; i < TQ * zc4; i += THREADS) {
                int r = i / zc4;
                int cc = i - r * zc4;
                *(float4*)(base + (size_t)r * NSEQ + cc * 4) = z4;
            }
        }
    }

    // ---- write O (normalized) ----
    float* orow_a = gout + ((size_t)b * NSEQ + gi0) * DHEAD;
    float* orow_b = orow_a + 8 * DHEAD;
#pragma unroll
    for (int nf = 0; nf < 16; nf++) {
        int d0 = nf * 8 + 2 * lr;
        *(float2*)(orow_a + d0) = make_float2(o[nf][0] * linv_a, o[nf][1] * linv_a);
        *(float2*)(orow_b + d0) = make_float2(o[nf][2] * linv_b, o[nf][3] * linv_b);
    }
}

// rescale the causal (lower-triangular) part of attn by 1/l; one warp per row
__global__ void __launch_bounds__(256)
rescale_kernel(float* __restrict__ gattn) {
    const int row = blockIdx.x * 8 + (threadIdx.x >> 5);  // b*NSEQ + i
    const int lane = threadIdx.x & 31;
    const int i = row & (NSEQ - 1);
    const float linv = g_linv[row];
    float* p = gattn + (size_t)row * NSEQ;
    const int n = i + 1;          // valid entries: j in [0, i]
    const int nvec = n & ~3;      // float4-aligned prefix
    for (int j = lane * 4; j < nvec; j += 128) {
        float4 v = *(float4*)(p + j);
        v.x *= linv; v.y *= linv; v.z *= linv; v.w *= linv;
        *(float4*)(p + j) = v;
    }
    if (lane < (n - nvec)) {
        p[nvec + lane] *= linv;
    }
}

extern "C" void kernel_launch(void* const* d_in, const int* in_sizes, int n_in,
                              void* d_out, int out_size) {
    const float* q = (const float*)d_in[0];
    const float* k = (const float*)d_in[1];
    const float* v = (const float*)d_in[2];
    // mask (d_in[3]) is a fixed causal mask; applied analytically in-kernel.
    float* attn = (float*)d_out;
    float* out = attn + (size_t)BATCH * NSEQ * NSEQ;

    cudaFuncSetAttribute(attn_kernel, cudaFuncAttributeMaxDynamicSharedMemorySize, SM_BYTES);
    dim3 grid(NSEQ / TQ, BATCH);
    attn_kernel<<<grid, THREADS, SM_BYTES>>>(q, k, v, attn, out);

    // normalize the causal part of attn (masked part is already exact zeros)
    rescale_kernel<<<(BATCH * NSEQ) / 8, 256>>>(attn);
}